// round 6
// baseline (speedup 1.0000x reference)
#include <cuda_runtime.h>
#include <cuda_fp16.h>
#include <cstdint>

// ============================================================================
// EdgeMLP: out = silu( silu(LN(concat(src,edge) @ W1 + b1)) @ W2 + b2 )
// E rows; in 192 (128 src + 64 edge), hid/out 128.
//
// R6 (from R5 profile: occ 24.5%, issue 37%, L1 61%, DRAM 29% - latency bound,
// occupancy capped by regs): cut issue slots + hide LDG latency.
//   - K-permuted GEMM1 fragments: thread's 4 A halves per k16-tile are one
//     contiguous float4 -> 24 LDG.128 instead of 48 LDG.64
//   - N-permuted outputs: thread's 4 C values per n16-pair contiguous ->
//     16 STG.128 instead of 32 STG.64; bias/gamma/beta reads via float4.
//     GEMM1-N perm == GEMM2-K perm, so register C->A handoff stays free.
//   - software pipeline: next group's A prefetched (packed, 48 regs) between
//     GEMM2 and epilogue2 -> DRAM latency hidden under silu epilogue
// ============================================================================

static constexpr int NT1 = 16;   // 16 n8-tiles  -> N=128
static constexpr int NP1 = 8;    // 8 n16 pairs
static constexpr int KT1 = 12;   // 12 k16-tiles -> K=192
static constexpr int KT2 = 8;    // K=128
static constexpr float LN_EPS = 1e-5f;

// dynamic smem layout (bytes)
static constexpr int SM_W1F = 0;                              // 12*8*32 uint4 = 49152
static constexpr int SM_W2F = SM_W1F + KT1 * NP1 * 32 * 16;   // 49152
static constexpr int SM_B1  = SM_W2F + KT2 * NP1 * 32 * 16;   // 81920
static constexpr int SM_GM  = SM_B1 + 512;
static constexpr int SM_BT  = SM_GM + 512;
static constexpr int SM_B2  = SM_BT + 512;
static constexpr int SMEM_BYTES = SM_B2 + 512;                // 83968

__device__ __forceinline__ uint32_t packh2(float a, float b) {
    __half2 h = __floats2half2_rn(a, b);
    return *reinterpret_cast<uint32_t*>(&h);
}

__device__ __forceinline__ void mma16816(float c[4],
                                         uint32_t a0, uint32_t a1, uint32_t a2, uint32_t a3,
                                         uint32_t b0, uint32_t b1) {
    asm volatile(
        "mma.sync.aligned.m16n8k16.row.col.f32.f16.f16.f32 "
        "{%0,%1,%2,%3}, {%4,%5,%6,%7}, {%8,%9}, {%0,%1,%2,%3};"
        : "+f"(c[0]), "+f"(c[1]), "+f"(c[2]), "+f"(c[3])
        : "r"(a0), "r"(a1), "r"(a2), "r"(a3), "r"(b0), "r"(b1));
}

__device__ __forceinline__ float silu(float y) {
    return y / (1.0f + __expf(-y));
}

// Load + pack one 16-row group's A operands (K-permuted: thread c4 owns
// physical cols {base+4c4 .. +3} of each k16 tile -> float4 loads).
__device__ __forceinline__ void load_group(const float* __restrict__ src,
                                           const float* __restrict__ edg,
                                           size_t r0, size_t r1, int c4,
                                           uint32_t apre[KT1][4]) {
    #pragma unroll
    for (int kt = 0; kt < 8; kt++) {
        float4 v = *reinterpret_cast<const float4*>(src + r0 * 128 + kt * 16 + 4 * c4);
        float4 w = *reinterpret_cast<const float4*>(src + r1 * 128 + kt * 16 + 4 * c4);
        apre[kt][0] = packh2(v.x, v.y);   // a0: k-pos 2c4,2c4+1  = phys +0,+1
        apre[kt][2] = packh2(v.z, v.w);   // a2: k-pos 2c4+8,+9   = phys +2,+3
        apre[kt][1] = packh2(w.x, w.y);   // a1: rows +8
        apre[kt][3] = packh2(w.z, w.w);   // a3
    }
    #pragma unroll
    for (int kt = 8; kt < 12; kt++) {
        float4 v = *reinterpret_cast<const float4*>(edg + r0 * 64 + (kt - 8) * 16 + 4 * c4);
        float4 w = *reinterpret_cast<const float4*>(edg + r1 * 64 + (kt - 8) * 16 + 4 * c4);
        apre[kt][0] = packh2(v.x, v.y);
        apre[kt][2] = packh2(v.z, v.w);
        apre[kt][1] = packh2(w.x, w.y);
        apre[kt][3] = packh2(w.z, w.w);
    }
}

__global__ void __launch_bounds__(256, 2) edge_mlp_kernel(
    const float* __restrict__ src, const float* __restrict__ edg,
    const float* __restrict__ W1, const float* __restrict__ b1,
    const float* __restrict__ gma, const float* __restrict__ bta,
    const float* __restrict__ W2, const float* __restrict__ b2,
    float* __restrict__ out, int E, int n_groups)
{
    extern __shared__ char smem[];
    uint4* w1f = reinterpret_cast<uint4*>(smem + SM_W1F);
    uint4* w2f = reinterpret_cast<uint4*>(smem + SM_W2F);
    float* b1s = reinterpret_cast<float*>(smem + SM_B1);
    float* gms = reinterpret_cast<float*>(smem + SM_GM);
    float* bts = reinterpret_cast<float*>(smem + SM_BT);
    float* b2s = reinterpret_cast<float*>(smem + SM_B2);

    const int tid  = threadIdx.x;
    const int lane = tid & 31;
    const int wid  = tid >> 5;
    const int q    = lane >> 2;   // 0..7  (row within m16: q and q+8; also B n-pos)
    const int c4   = lane & 3;    // 0..3

    // ---- one-time: params + fragment-order weight swizzle into smem ----
    for (int i = tid; i < 128; i += 256) {
        b1s[i] = b1[i];
        gms[i] = gma[i];
        bts[i] = bta[i];
        b2s[i] = b2[i];
    }
    // B fragments, K-permuted and N-permuted.
    //   K perm: positions (2c4,2c4+1 | 2c4+8,2c4+9) hold phys k = 16kt+4c4 + (0,1 | 2,3)
    //   N perm: tile 2np pos p -> phys col 16np + 4*(p>>1) + (p&1)
    //           tile 2np+1 pos p -> phys col 16np + 4*(p>>1) + 2 + (p&1)
    //   B lane n-pos = lane>>2. uint4 = {b0(n0), b1(n0), b0(n1), b1(n1)}.
    for (int e = tid; e < KT1 * NP1 * 32; e += 256) {
        int l = e & 31, slot = e >> 5;
        int np = slot & 7, kt = slot >> 3;
        int k = kt * 16 + 4 * (l & 3);
        int qq = l >> 2;
        int n0 = np * 16 + 4 * (qq >> 1) + (qq & 1);
        int n1 = n0 + 2;
        uint4 v;
        v.x = packh2(W1[k * 128 + n0], W1[(k + 1) * 128 + n0]);
        v.y = packh2(W1[(k + 2) * 128 + n0], W1[(k + 3) * 128 + n0]);
        v.z = packh2(W1[k * 128 + n1], W1[(k + 1) * 128 + n1]);
        v.w = packh2(W1[(k + 2) * 128 + n1], W1[(k + 3) * 128 + n1]);
        w1f[e] = v;
    }
    // GEMM2: K perm must equal GEMM1's N perm (it does — same formula), and we
    // apply the same N perm again for float4 stores.
    for (int e = tid; e < KT2 * NP1 * 32; e += 256) {
        int l = e & 31, slot = e >> 5;
        int np = slot & 7, kt = slot >> 3;
        int k = kt * 16 + 4 * (l & 3);
        int qq = l >> 2;
        int n0 = np * 16 + 4 * (qq >> 1) + (qq & 1);
        int n1 = n0 + 2;
        uint4 v;
        v.x = packh2(W2[k * 128 + n0], W2[(k + 1) * 128 + n0]);
        v.y = packh2(W2[(k + 2) * 128 + n0], W2[(k + 3) * 128 + n0]);
        v.z = packh2(W2[k * 128 + n1], W2[(k + 1) * 128 + n1]);
        v.w = packh2(W2[(k + 2) * 128 + n1], W2[(k + 3) * 128 + n1]);
        w2f[e] = v;
    }
    __syncthreads();

    // ---- persistent loop: each warp processes independent 16-row groups ----
    const int warp_global = blockIdx.x * 8 + wid;
    const int warp_step   = gridDim.x * 8;

    uint32_t apre[KT1][4];
    if (warp_global < n_groups) {
        size_t r0 = (size_t)min(warp_global * 16 + q, E - 1);
        load_group(src, edg, r0, r0 + 8, c4, apre);  // E%16==0: r0+8 < E always when r0 valid
    }

    for (int g = warp_global; g < n_groups; g += warp_step) {
        const int row0 = g * 16 + q;
        const int row1 = row0 + 8;

        // ================= GEMM1: [16x192] @ W1 -> acc[16 nt][4] =================
        float acc[NT1][4];
        #pragma unroll
        for (int nt = 0; nt < NT1; nt++) {
            acc[nt][0] = 0.f; acc[nt][1] = 0.f; acc[nt][2] = 0.f; acc[nt][3] = 0.f;
        }
        #pragma unroll
        for (int kt = 0; kt < KT1; kt++) {
            const uint4* wrow = w1f + (kt * NP1) * 32 + lane;
            #pragma unroll
            for (int np = 0; np < NP1; np++) {
                uint4 B = wrow[np * 32];
                mma16816(acc[2 * np],     apre[kt][0], apre[kt][1], apre[kt][2], apre[kt][3], B.x, B.y);
                mma16816(acc[2 * np + 1], apre[kt][0], apre[kt][1], apre[kt][2], apre[kt][3], B.z, B.w);
            }
        }

        // ================= epilogue 1: +b1, LayerNorm, SiLU =================
        // phys cols for (np,c4): tile 2np c0/c1 -> 16np+4c4 +0/+1; tile 2np+1 -> +2/+3
        float s0 = 0.f, s1 = 0.f;
        #pragma unroll
        for (int np = 0; np < NP1; np++) {
            float4 bb = *reinterpret_cast<const float4*>(b1s + 16 * np + 4 * c4);
            acc[2*np][0]   += bb.x; acc[2*np][1]   += bb.y;
            acc[2*np][2]   += bb.x; acc[2*np][3]   += bb.y;
            acc[2*np+1][0] += bb.z; acc[2*np+1][1] += bb.w;
            acc[2*np+1][2] += bb.z; acc[2*np+1][3] += bb.w;
            s0 += acc[2*np][0] + acc[2*np][1] + acc[2*np+1][0] + acc[2*np+1][1];
            s1 += acc[2*np][2] + acc[2*np][3] + acc[2*np+1][2] + acc[2*np+1][3];
        }
        s0 += __shfl_xor_sync(0xffffffffu, s0, 1);
        s0 += __shfl_xor_sync(0xffffffffu, s0, 2);
        s1 += __shfl_xor_sync(0xffffffffu, s1, 1);
        s1 += __shfl_xor_sync(0xffffffffu, s1, 2);
        const float mu0 = s0 * (1.f / 128.f);
        const float mu1 = s1 * (1.f / 128.f);

        float v0 = 0.f, v1 = 0.f;
        #pragma unroll
        for (int nt = 0; nt < NT1; nt++) {
            float d0 = acc[nt][0] - mu0, d1 = acc[nt][1] - mu0;
            float d2 = acc[nt][2] - mu1, d3 = acc[nt][3] - mu1;
            v0 += d0 * d0 + d1 * d1;
            v1 += d2 * d2 + d3 * d3;
        }
        v0 += __shfl_xor_sync(0xffffffffu, v0, 1);
        v0 += __shfl_xor_sync(0xffffffffu, v0, 2);
        v1 += __shfl_xor_sync(0xffffffffu, v1, 1);
        v1 += __shfl_xor_sync(0xffffffffu, v1, 2);
        const float rs0 = rsqrtf(v0 * (1.f / 128.f) + LN_EPS);
        const float rs1 = rsqrtf(v1 * (1.f / 128.f) + LN_EPS);

        // C (N-permuted) -> A fragment of GEMM2 (K-permuted identically): free.
        uint32_t a2f[KT2][4];
        #pragma unroll
        for (int np = 0; np < NP1; np++) {
            float4 gg  = *reinterpret_cast<const float4*>(gms + 16 * np + 4 * c4);
            float4 bt4 = *reinterpret_cast<const float4*>(bts + 16 * np + 4 * c4);
            float y00 = silu((acc[2*np][0]   - mu0) * rs0 * gg.x + bt4.x);
            float y01 = silu((acc[2*np][1]   - mu0) * rs0 * gg.y + bt4.y);
            float y10 = silu((acc[2*np][2]   - mu1) * rs1 * gg.x + bt4.x);
            float y11 = silu((acc[2*np][3]   - mu1) * rs1 * gg.y + bt4.y);
            float z00 = silu((acc[2*np+1][0] - mu0) * rs0 * gg.z + bt4.z);
            float z01 = silu((acc[2*np+1][1] - mu0) * rs0 * gg.w + bt4.w);
            float z10 = silu((acc[2*np+1][2] - mu1) * rs1 * gg.z + bt4.z);
            float z11 = silu((acc[2*np+1][3] - mu1) * rs1 * gg.w + bt4.w);
            a2f[np][0] = packh2(y00, y01);  // a0: phys k 16np+4c4 +0,+1, rows q
            a2f[np][1] = packh2(y10, y11);  // a1: rows q+8
            a2f[np][2] = packh2(z00, z01);  // a2: phys +2,+3
            a2f[np][3] = packh2(z10, z11);  // a3
        }

        // ================= GEMM2: [16x128] @ W2 -> acc (reused) =================
        #pragma unroll
        for (int nt = 0; nt < NT1; nt++) {
            acc[nt][0] = 0.f; acc[nt][1] = 0.f; acc[nt][2] = 0.f; acc[nt][3] = 0.f;
        }
        #pragma unroll
        for (int kt = 0; kt < KT2; kt++) {
            const uint4* wrow = w2f + (kt * NP1) * 32 + lane;
            #pragma unroll
            for (int np = 0; np < NP1; np++) {
                uint4 B = wrow[np * 32];
                mma16816(acc[2 * np],     a2f[kt][0], a2f[kt][1], a2f[kt][2], a2f[kt][3], B.x, B.y);
                mma16816(acc[2 * np + 1], a2f[kt][0], a2f[kt][1], a2f[kt][2], a2f[kt][3], B.z, B.w);
            }
        }

        // ---- prefetch next group's A while epilogue 2 runs ----
        {
            int gc = g + warp_step;
            if (gc > n_groups - 1) gc = n_groups - 1;   // clamped dummy on last iter
            size_t nr0 = (size_t)min(gc * 16 + q, E - 1);
            size_t nr1 = (size_t)min(gc * 16 + q + 8, E - 1);
            load_group(src, edg, nr0, nr1, c4, apre);
        }

        // ================= epilogue 2: +b2, SiLU, store (float4) =================
        const bool val0 = (row0 < E);
        const bool val1 = (row1 < E);
        #pragma unroll
        for (int np = 0; np < NP1; np++) {
            float4 bb = *reinterpret_cast<const float4*>(b2s + 16 * np + 4 * c4);
            float4 o0, o1;
            o0.x = silu(acc[2*np][0]   + bb.x);
            o0.y = silu(acc[2*np][1]   + bb.y);
            o0.z = silu(acc[2*np+1][0] + bb.z);
            o0.w = silu(acc[2*np+1][1] + bb.w);
            o1.x = silu(acc[2*np][2]   + bb.x);
            o1.y = silu(acc[2*np][3]   + bb.y);
            o1.z = silu(acc[2*np+1][2] + bb.z);
            o1.w = silu(acc[2*np+1][3] + bb.w);
            const int col = 16 * np + 4 * c4;
            if (val0) *reinterpret_cast<float4*>(out + (size_t)row0 * 128 + col) = o0;
            if (val1) *reinterpret_cast<float4*>(out + (size_t)row1 * 128 + col) = o1;
        }
    }
}

// ===================== launch =====================
extern "C" void kernel_launch(void* const* d_in, const int* in_sizes, int n_in,
                              void* d_out, int out_size)
{
    (void)n_in; (void)out_size;
    const float* src = (const float*)d_in[0];
    const float* edg = (const float*)d_in[1];
    const float* W1  = (const float*)d_in[2];
    const float* b1  = (const float*)d_in[3];
    const float* gma = (const float*)d_in[4];
    const float* bta = (const float*)d_in[5];
    const float* W2  = (const float*)d_in[6];
    const float* b2  = (const float*)d_in[7];
    float* out = (float*)d_out;

    const int E = in_sizes[0] / 128;
    const int n_groups = (E + 15) / 16;

    cudaFuncSetAttribute(edge_mlp_kernel,
                         cudaFuncAttributeMaxDynamicSharedMemorySize, SMEM_BYTES);
    edge_mlp_kernel<<<304, 256, SMEM_BYTES>>>(src, edg, W1, b1, gma, bta, W2, b2,
                                              out, E, n_groups);
}

// round 7
// speedup vs baseline: 2.4045x; 2.4045x over previous
#include <cuda_runtime.h>
#include <cuda_fp16.h>
#include <cstdint>

// ============================================================================
// EdgeMLP: out = silu( silu(LN(concat(src,edge) @ W1 + b1)) @ W2 + b2 )
// E rows; in 192 (128 src + 64 edge), hid/out 128.
//
// R7 = R5 structure + R6's fragment permutations, WITHOUT the R6 prefetch
// (prefetch held 48 extra regs across GEMM2 -> spills -> 410us regression).
//   - K-permuted GEMM1 A fragments: 24 LDG.128 per group (was 48 LDG.64)
//   - N-permuted outputs: 16 STG.128 per group (was 32 STG.64)
//   - GEMM1-N perm == GEMM2-K perm -> register C->A handoff stays free
//   - A loaded at loop top (no live range across GEMM2), acc reused
//   - __fdividef in silu (MUFU.RCP vs expanded IEEE divide)
// ============================================================================

static constexpr int NT1 = 16;   // 16 n8-tiles  -> N=128
static constexpr int NP1 = 8;    // 8 n16 pairs
static constexpr int KT1 = 12;   // 12 k16-tiles -> K=192
static constexpr int KT2 = 8;    // K=128
static constexpr float LN_EPS = 1e-5f;

// dynamic smem layout (bytes)
static constexpr int SM_W1F = 0;                              // 12*8*32 uint4 = 49152
static constexpr int SM_W2F = SM_W1F + KT1 * NP1 * 32 * 16;   // 49152
static constexpr int SM_B1  = SM_W2F + KT2 * NP1 * 32 * 16;   // 81920
static constexpr int SM_GM  = SM_B1 + 512;
static constexpr int SM_BT  = SM_GM + 512;
static constexpr int SM_B2  = SM_BT + 512;
static constexpr int SMEM_BYTES = SM_B2 + 512;                // 83968

__device__ __forceinline__ uint32_t packh2(float a, float b) {
    __half2 h = __floats2half2_rn(a, b);
    return *reinterpret_cast<uint32_t*>(&h);
}

__device__ __forceinline__ void mma16816(float c[4],
                                         uint32_t a0, uint32_t a1, uint32_t a2, uint32_t a3,
                                         uint32_t b0, uint32_t b1) {
    asm volatile(
        "mma.sync.aligned.m16n8k16.row.col.f32.f16.f16.f32 "
        "{%0,%1,%2,%3}, {%4,%5,%6,%7}, {%8,%9}, {%0,%1,%2,%3};"
        : "+f"(c[0]), "+f"(c[1]), "+f"(c[2]), "+f"(c[3])
        : "r"(a0), "r"(a1), "r"(a2), "r"(a3), "r"(b0), "r"(b1));
}

__device__ __forceinline__ float silu(float y) {
    return __fdividef(y, 1.0f + __expf(-y));
}

__global__ void __launch_bounds__(256, 2) edge_mlp_kernel(
    const float* __restrict__ src, const float* __restrict__ edg,
    const float* __restrict__ W1, const float* __restrict__ b1,
    const float* __restrict__ gma, const float* __restrict__ bta,
    const float* __restrict__ W2, const float* __restrict__ b2,
    float* __restrict__ out, int E, int n_groups)
{
    extern __shared__ char smem[];
    uint4* w1f = reinterpret_cast<uint4*>(smem + SM_W1F);
    uint4* w2f = reinterpret_cast<uint4*>(smem + SM_W2F);
    float* b1s = reinterpret_cast<float*>(smem + SM_B1);
    float* gms = reinterpret_cast<float*>(smem + SM_GM);
    float* bts = reinterpret_cast<float*>(smem + SM_BT);
    float* b2s = reinterpret_cast<float*>(smem + SM_B2);

    const int tid  = threadIdx.x;
    const int lane = tid & 31;
    const int wid  = tid >> 5;
    const int q    = lane >> 2;   // 0..7  (row within m16: q and q+8; also B n-pos)
    const int c4   = lane & 3;    // 0..3

    // ---- one-time: params + fragment-order weight swizzle into smem ----
    for (int i = tid; i < 128; i += 256) {
        b1s[i] = b1[i];
        gms[i] = gma[i];
        bts[i] = bta[i];
        b2s[i] = b2[i];
    }
    // B fragments, K-permuted and N-permuted.
    //   K perm: fragment k-positions (2c4,2c4+1 | 2c4+8,2c4+9) hold
    //           phys k = 16kt + 4c4 + (0,1 | 2,3)
    //   N perm: tile 2np pos p -> phys col 16np + 4*(p>>1) + (p&1)
    //           tile 2np+1 pos p -> phys col 16np + 4*(p>>1) + 2 + (p&1)
    //   B lane n-pos = lane>>2. uint4 = {b0(n0), b1(n0), b0(n1), b1(n1)}.
    for (int e = tid; e < KT1 * NP1 * 32; e += 256) {
        int l = e & 31, slot = e >> 5;
        int np = slot & 7, kt = slot >> 3;
        int k = kt * 16 + 4 * (l & 3);
        int qq = l >> 2;
        int n0 = np * 16 + 4 * (qq >> 1) + (qq & 1);
        int n1 = n0 + 2;
        uint4 v;
        v.x = packh2(W1[k * 128 + n0], W1[(k + 1) * 128 + n0]);
        v.y = packh2(W1[(k + 2) * 128 + n0], W1[(k + 3) * 128 + n0]);
        v.z = packh2(W1[k * 128 + n1], W1[(k + 1) * 128 + n1]);
        v.w = packh2(W1[(k + 2) * 128 + n1], W1[(k + 3) * 128 + n1]);
        w1f[e] = v;
    }
    // GEMM2: K perm == GEMM1's N perm (same formula); same N perm for stores.
    for (int e = tid; e < KT2 * NP1 * 32; e += 256) {
        int l = e & 31, slot = e >> 5;
        int np = slot & 7, kt = slot >> 3;
        int k = kt * 16 + 4 * (l & 3);
        int qq = l >> 2;
        int n0 = np * 16 + 4 * (qq >> 1) + (qq & 1);
        int n1 = n0 + 2;
        uint4 v;
        v.x = packh2(W2[k * 128 + n0], W2[(k + 1) * 128 + n0]);
        v.y = packh2(W2[(k + 2) * 128 + n0], W2[(k + 3) * 128 + n0]);
        v.z = packh2(W2[k * 128 + n1], W2[(k + 1) * 128 + n1]);
        v.w = packh2(W2[(k + 2) * 128 + n1], W2[(k + 3) * 128 + n1]);
        w2f[e] = v;
    }
    __syncthreads();

    // ---- persistent loop: each warp processes independent 16-row groups ----
    const int warp_global = blockIdx.x * 8 + wid;
    const int warp_step   = gridDim.x * 8;

    for (int g = warp_global; g < n_groups; g += warp_step) {
        const int row0 = g * 16 + q;
        const int row1 = row0 + 8;
        const size_t r0 = (size_t)min(row0, E - 1);
        const size_t r1 = (size_t)min(row1, E - 1);

        // ---- load A (K-permuted, float4) ----
        uint32_t af[KT1][4];
        #pragma unroll
        for (int kt = 0; kt < 8; kt++) {
            float4 v = *reinterpret_cast<const float4*>(src + r0 * 128 + kt * 16 + 4 * c4);
            float4 w = *reinterpret_cast<const float4*>(src + r1 * 128 + kt * 16 + 4 * c4);
            af[kt][0] = packh2(v.x, v.y);   // a0: frag k-pos 2c4,2c4+1 = phys +0,+1
            af[kt][2] = packh2(v.z, v.w);   // a2: frag k-pos +8,+9     = phys +2,+3
            af[kt][1] = packh2(w.x, w.y);   // a1: rows +8
            af[kt][3] = packh2(w.z, w.w);   // a3
        }
        #pragma unroll
        for (int kt = 8; kt < 12; kt++) {
            float4 v = *reinterpret_cast<const float4*>(edg + r0 * 64 + (kt - 8) * 16 + 4 * c4);
            float4 w = *reinterpret_cast<const float4*>(edg + r1 * 64 + (kt - 8) * 16 + 4 * c4);
            af[kt][0] = packh2(v.x, v.y);
            af[kt][2] = packh2(v.z, v.w);
            af[kt][1] = packh2(w.x, w.y);
            af[kt][3] = packh2(w.z, w.w);
        }

        // ================= GEMM1: [16x192] @ W1 -> acc[16 nt][4] =================
        float acc[NT1][4];
        #pragma unroll
        for (int nt = 0; nt < NT1; nt++) {
            acc[nt][0] = 0.f; acc[nt][1] = 0.f; acc[nt][2] = 0.f; acc[nt][3] = 0.f;
        }
        #pragma unroll
        for (int kt = 0; kt < KT1; kt++) {
            const uint4* wrow = w1f + (kt * NP1) * 32 + lane;
            #pragma unroll
            for (int np = 0; np < NP1; np++) {
                uint4 B = wrow[np * 32];
                mma16816(acc[2 * np],     af[kt][0], af[kt][1], af[kt][2], af[kt][3], B.x, B.y);
                mma16816(acc[2 * np + 1], af[kt][0], af[kt][1], af[kt][2], af[kt][3], B.z, B.w);
            }
        }

        // ================= epilogue 1: +b1, LayerNorm, SiLU =================
        float s0 = 0.f, s1 = 0.f;
        #pragma unroll
        for (int np = 0; np < NP1; np++) {
            float4 bb = *reinterpret_cast<const float4*>(b1s + 16 * np + 4 * c4);
            acc[2*np][0]   += bb.x; acc[2*np][1]   += bb.y;
            acc[2*np][2]   += bb.x; acc[2*np][3]   += bb.y;
            acc[2*np+1][0] += bb.z; acc[2*np+1][1] += bb.w;
            acc[2*np+1][2] += bb.z; acc[2*np+1][3] += bb.w;
            s0 += acc[2*np][0] + acc[2*np][1] + acc[2*np+1][0] + acc[2*np+1][1];
            s1 += acc[2*np][2] + acc[2*np][3] + acc[2*np+1][2] + acc[2*np+1][3];
        }
        s0 += __shfl_xor_sync(0xffffffffu, s0, 1);
        s0 += __shfl_xor_sync(0xffffffffu, s0, 2);
        s1 += __shfl_xor_sync(0xffffffffu, s1, 1);
        s1 += __shfl_xor_sync(0xffffffffu, s1, 2);
        const float mu0 = s0 * (1.f / 128.f);
        const float mu1 = s1 * (1.f / 128.f);

        float v0 = 0.f, v1 = 0.f;
        #pragma unroll
        for (int nt = 0; nt < NT1; nt++) {
            float d0 = acc[nt][0] - mu0, d1 = acc[nt][1] - mu0;
            float d2 = acc[nt][2] - mu1, d3 = acc[nt][3] - mu1;
            v0 += d0 * d0 + d1 * d1;
            v1 += d2 * d2 + d3 * d3;
        }
        v0 += __shfl_xor_sync(0xffffffffu, v0, 1);
        v0 += __shfl_xor_sync(0xffffffffu, v0, 2);
        v1 += __shfl_xor_sync(0xffffffffu, v1, 1);
        v1 += __shfl_xor_sync(0xffffffffu, v1, 2);
        const float rs0 = rsqrtf(v0 * (1.f / 128.f) + LN_EPS);
        const float rs1 = rsqrtf(v1 * (1.f / 128.f) + LN_EPS);

        // C (N-permuted) -> A fragment of GEMM2 (K-permuted identically): free.
        uint32_t a2f[KT2][4];
        #pragma unroll
        for (int np = 0; np < NP1; np++) {
            float4 gg  = *reinterpret_cast<const float4*>(gms + 16 * np + 4 * c4);
            float4 bt4 = *reinterpret_cast<const float4*>(bts + 16 * np + 4 * c4);
            float y00 = silu((acc[2*np][0]   - mu0) * rs0 * gg.x + bt4.x);
            float y01 = silu((acc[2*np][1]   - mu0) * rs0 * gg.y + bt4.y);
            float y10 = silu((acc[2*np][2]   - mu1) * rs1 * gg.x + bt4.x);
            float y11 = silu((acc[2*np][3]   - mu1) * rs1 * gg.y + bt4.y);
            float z00 = silu((acc[2*np+1][0] - mu0) * rs0 * gg.z + bt4.z);
            float z01 = silu((acc[2*np+1][1] - mu0) * rs0 * gg.w + bt4.w);
            float z10 = silu((acc[2*np+1][2] - mu1) * rs1 * gg.z + bt4.z);
            float z11 = silu((acc[2*np+1][3] - mu1) * rs1 * gg.w + bt4.w);
            a2f[np][0] = packh2(y00, y01);  // a0
            a2f[np][1] = packh2(y10, y11);  // a1 (rows +8)
            a2f[np][2] = packh2(z00, z01);  // a2
            a2f[np][3] = packh2(z10, z11);  // a3
        }

        // ================= GEMM2: [16x128] @ W2 -> acc (reused) =================
        #pragma unroll
        for (int nt = 0; nt < NT1; nt++) {
            acc[nt][0] = 0.f; acc[nt][1] = 0.f; acc[nt][2] = 0.f; acc[nt][3] = 0.f;
        }
        #pragma unroll
        for (int kt = 0; kt < KT2; kt++) {
            const uint4* wrow = w2f + (kt * NP1) * 32 + lane;
            #pragma unroll
            for (int np = 0; np < NP1; np++) {
                uint4 B = wrow[np * 32];
                mma16816(acc[2 * np],     a2f[kt][0], a2f[kt][1], a2f[kt][2], a2f[kt][3], B.x, B.y);
                mma16816(acc[2 * np + 1], a2f[kt][0], a2f[kt][1], a2f[kt][2], a2f[kt][3], B.z, B.w);
            }
        }

        // ================= epilogue 2: +b2, SiLU, store (float4) =================
        const bool val0 = (row0 < E);
        const bool val1 = (row1 < E);
        #pragma unroll
        for (int np = 0; np < NP1; np++) {
            float4 bb = *reinterpret_cast<const float4*>(b2s + 16 * np + 4 * c4);
            float4 o0, o1;
            o0.x = silu(acc[2*np][0]   + bb.x);
            o0.y = silu(acc[2*np][1]   + bb.y);
            o0.z = silu(acc[2*np+1][0] + bb.z);
            o0.w = silu(acc[2*np+1][1] + bb.w);
            o1.x = silu(acc[2*np][2]   + bb.x);
            o1.y = silu(acc[2*np][3]   + bb.y);
            o1.z = silu(acc[2*np+1][2] + bb.z);
            o1.w = silu(acc[2*np+1][3] + bb.w);
            const int col = 16 * np + 4 * c4;
            if (val0) *reinterpret_cast<float4*>(out + (size_t)row0 * 128 + col) = o0;
            if (val1) *reinterpret_cast<float4*>(out + (size_t)row1 * 128 + col) = o1;
        }
    }
}

// ===================== launch =====================
extern "C" void kernel_launch(void* const* d_in, const int* in_sizes, int n_in,
                              void* d_out, int out_size)
{
    (void)n_in; (void)out_size;
    const float* src = (const float*)d_in[0];
    const float* edg = (const float*)d_in[1];
    const float* W1  = (const float*)d_in[2];
    const float* b1  = (const float*)d_in[3];
    const float* gma = (const float*)d_in[4];
    const float* bta = (const float*)d_in[5];
    const float* W2  = (const float*)d_in[6];
    const float* b2  = (const float*)d_in[7];
    float* out = (float*)d_out;

    const int E = in_sizes[0] / 128;
    const int n_groups = (E + 15) / 16;

    cudaFuncSetAttribute(edge_mlp_kernel,
                         cudaFuncAttributeMaxDynamicSharedMemorySize, SMEM_BYTES);
    edge_mlp_kernel<<<304, 256, SMEM_BYTES>>>(src, edg, W1, b1, gma, bta, W2, b2,
                                              out, E, n_groups);
}

// round 8
// speedup vs baseline: 2.5949x; 1.0792x over previous
#include <cuda_runtime.h>
#include <cuda_fp16.h>
#include <cstdint>

// ============================================================================
// EdgeMLP: out = silu( silu(LN(concat(src,edge) @ W1 + b1)) @ W2 + b2 )
// E rows; in 192 (128 src + 64 edge), hid/out 128.
//
// R8 = R7 + epilogue diet (R7 profile: L1 81%, tensor 40%, DRAM 44%, issue 39%;
// hidden binder: ~512 MUFU/group (EX2+RCP per silu) ~ 65% MUFU utilization).
//   - silu via tanh.approx.f32: 1 MUFU + 2 FMA per element (was 2 MUFU + 4)
//   - one-pass LN moments: var = E[h^2] - mu^2, deletes 2nd 128-elem pass
//   - unchanged: K/N-permuted fragments (24 LDG.128 / 16 STG.128 per group),
//     warp-owned 16-row groups, fragment-order weights in smem, acc reuse,
//     no prefetch across GEMM2 (R6 spill lesson), no syncs in main loop
// ============================================================================

static constexpr int NT1 = 16;   // 16 n8-tiles  -> N=128
static constexpr int NP1 = 8;    // 8 n16 pairs
static constexpr int KT1 = 12;   // 12 k16-tiles -> K=192
static constexpr int KT2 = 8;    // K=128
static constexpr float LN_EPS = 1e-5f;

// dynamic smem layout (bytes)
static constexpr int SM_W1F = 0;                              // 12*8*32 uint4 = 49152
static constexpr int SM_W2F = SM_W1F + KT1 * NP1 * 32 * 16;   // 49152
static constexpr int SM_B1  = SM_W2F + KT2 * NP1 * 32 * 16;   // 81920
static constexpr int SM_GM  = SM_B1 + 512;
static constexpr int SM_BT  = SM_GM + 512;
static constexpr int SM_B2  = SM_BT + 512;
static constexpr int SMEM_BYTES = SM_B2 + 512;                // 83968

__device__ __forceinline__ uint32_t packh2(float a, float b) {
    __half2 h = __floats2half2_rn(a, b);
    return *reinterpret_cast<uint32_t*>(&h);
}

__device__ __forceinline__ void mma16816(float c[4],
                                         uint32_t a0, uint32_t a1, uint32_t a2, uint32_t a3,
                                         uint32_t b0, uint32_t b1) {
    asm volatile(
        "mma.sync.aligned.m16n8k16.row.col.f32.f16.f16.f32 "
        "{%0,%1,%2,%3}, {%4,%5,%6,%7}, {%8,%9}, {%0,%1,%2,%3};"
        : "+f"(c[0]), "+f"(c[1]), "+f"(c[2]), "+f"(c[3])
        : "r"(a0), "r"(a1), "r"(a2), "r"(a3), "r"(b0), "r"(b1));
}

// silu(x) = x * sigmoid(x) = 0.5x * (1 + tanh(x/2)) : 1 MUFU + 2 FMA-class ops
__device__ __forceinline__ float silu(float x) {
    float hx = 0.5f * x;
    float t;
    asm("tanh.approx.f32 %0, %1;" : "=f"(t) : "f"(hx));
    return fmaf(hx, t, hx);
}

__global__ void __launch_bounds__(256, 2) edge_mlp_kernel(
    const float* __restrict__ src, const float* __restrict__ edg,
    const float* __restrict__ W1, const float* __restrict__ b1,
    const float* __restrict__ gma, const float* __restrict__ bta,
    const float* __restrict__ W2, const float* __restrict__ b2,
    float* __restrict__ out, int E, int n_groups)
{
    extern __shared__ char smem[];
    uint4* w1f = reinterpret_cast<uint4*>(smem + SM_W1F);
    uint4* w2f = reinterpret_cast<uint4*>(smem + SM_W2F);
    float* b1s = reinterpret_cast<float*>(smem + SM_B1);
    float* gms = reinterpret_cast<float*>(smem + SM_GM);
    float* bts = reinterpret_cast<float*>(smem + SM_BT);
    float* b2s = reinterpret_cast<float*>(smem + SM_B2);

    const int tid  = threadIdx.x;
    const int lane = tid & 31;
    const int wid  = tid >> 5;
    const int q    = lane >> 2;   // 0..7  (row within m16: q and q+8; also B n-pos)
    const int c4   = lane & 3;    // 0..3

    // ---- one-time: params + fragment-order weight swizzle into smem ----
    for (int i = tid; i < 128; i += 256) {
        b1s[i] = b1[i];
        gms[i] = gma[i];
        bts[i] = bta[i];
        b2s[i] = b2[i];
    }
    // B fragments, K-permuted and N-permuted.
    //   K perm: fragment k-positions (2c4,2c4+1 | 2c4+8,2c4+9) hold
    //           phys k = 16kt + 4c4 + (0,1 | 2,3)
    //   N perm: tile 2np pos p -> phys col 16np + 4*(p>>1) + (p&1)
    //           tile 2np+1 pos p -> phys col 16np + 4*(p>>1) + 2 + (p&1)
    //   B lane n-pos = lane>>2. uint4 = {b0(n0), b1(n0), b0(n1), b1(n1)}.
    for (int e = tid; e < KT1 * NP1 * 32; e += 256) {
        int l = e & 31, slot = e >> 5;
        int np = slot & 7, kt = slot >> 3;
        int k = kt * 16 + 4 * (l & 3);
        int qq = l >> 2;
        int n0 = np * 16 + 4 * (qq >> 1) + (qq & 1);
        int n1 = n0 + 2;
        uint4 v;
        v.x = packh2(W1[k * 128 + n0], W1[(k + 1) * 128 + n0]);
        v.y = packh2(W1[(k + 2) * 128 + n0], W1[(k + 3) * 128 + n0]);
        v.z = packh2(W1[k * 128 + n1], W1[(k + 1) * 128 + n1]);
        v.w = packh2(W1[(k + 2) * 128 + n1], W1[(k + 3) * 128 + n1]);
        w1f[e] = v;
    }
    // GEMM2: K perm == GEMM1's N perm (same formula); same N perm for stores.
    for (int e = tid; e < KT2 * NP1 * 32; e += 256) {
        int l = e & 31, slot = e >> 5;
        int np = slot & 7, kt = slot >> 3;
        int k = kt * 16 + 4 * (l & 3);
        int qq = l >> 2;
        int n0 = np * 16 + 4 * (qq >> 1) + (qq & 1);
        int n1 = n0 + 2;
        uint4 v;
        v.x = packh2(W2[k * 128 + n0], W2[(k + 1) * 128 + n0]);
        v.y = packh2(W2[(k + 2) * 128 + n0], W2[(k + 3) * 128 + n0]);
        v.z = packh2(W2[k * 128 + n1], W2[(k + 1) * 128 + n1]);
        v.w = packh2(W2[(k + 2) * 128 + n1], W2[(k + 3) * 128 + n1]);
        w2f[e] = v;
    }
    __syncthreads();

    // ---- persistent loop: each warp processes independent 16-row groups ----
    const int warp_global = blockIdx.x * 8 + wid;
    const int warp_step   = gridDim.x * 8;

    for (int g = warp_global; g < n_groups; g += warp_step) {
        const int row0 = g * 16 + q;
        const int row1 = row0 + 8;
        const size_t r0 = (size_t)min(row0, E - 1);
        const size_t r1 = (size_t)min(row1, E - 1);

        // ---- load A (K-permuted, float4) ----
        uint32_t af[KT1][4];
        #pragma unroll
        for (int kt = 0; kt < 8; kt++) {
            float4 v = *reinterpret_cast<const float4*>(src + r0 * 128 + kt * 16 + 4 * c4);
            float4 w = *reinterpret_cast<const float4*>(src + r1 * 128 + kt * 16 + 4 * c4);
            af[kt][0] = packh2(v.x, v.y);   // a0: frag k-pos 2c4,2c4+1 = phys +0,+1
            af[kt][2] = packh2(v.z, v.w);   // a2: frag k-pos +8,+9     = phys +2,+3
            af[kt][1] = packh2(w.x, w.y);   // a1: rows +8
            af[kt][3] = packh2(w.z, w.w);   // a3
        }
        #pragma unroll
        for (int kt = 8; kt < 12; kt++) {
            float4 v = *reinterpret_cast<const float4*>(edg + r0 * 64 + (kt - 8) * 16 + 4 * c4);
            float4 w = *reinterpret_cast<const float4*>(edg + r1 * 64 + (kt - 8) * 16 + 4 * c4);
            af[kt][0] = packh2(v.x, v.y);
            af[kt][2] = packh2(v.z, v.w);
            af[kt][1] = packh2(w.x, w.y);
            af[kt][3] = packh2(w.z, w.w);
        }

        // ================= GEMM1: [16x192] @ W1 -> acc[16 nt][4] =================
        float acc[NT1][4];
        #pragma unroll
        for (int nt = 0; nt < NT1; nt++) {
            acc[nt][0] = 0.f; acc[nt][1] = 0.f; acc[nt][2] = 0.f; acc[nt][3] = 0.f;
        }
        #pragma unroll
        for (int kt = 0; kt < KT1; kt++) {
            const uint4* wrow = w1f + (kt * NP1) * 32 + lane;
            #pragma unroll
            for (int np = 0; np < NP1; np++) {
                uint4 B = wrow[np * 32];
                mma16816(acc[2 * np],     af[kt][0], af[kt][1], af[kt][2], af[kt][3], B.x, B.y);
                mma16816(acc[2 * np + 1], af[kt][0], af[kt][1], af[kt][2], af[kt][3], B.z, B.w);
            }
        }

        // ===== epilogue 1: +b1, one-pass LN moments (sum & sumsq), SiLU =====
        float s0 = 0.f, s1 = 0.f, ss0 = 0.f, ss1 = 0.f;
        #pragma unroll
        for (int np = 0; np < NP1; np++) {
            float4 bb = *reinterpret_cast<const float4*>(b1s + 16 * np + 4 * c4);
            acc[2*np][0]   += bb.x; acc[2*np][1]   += bb.y;
            acc[2*np][2]   += bb.x; acc[2*np][3]   += bb.y;
            acc[2*np+1][0] += bb.z; acc[2*np+1][1] += bb.w;
            acc[2*np+1][2] += bb.z; acc[2*np+1][3] += bb.w;
            s0 += acc[2*np][0] + acc[2*np][1] + acc[2*np+1][0] + acc[2*np+1][1];
            s1 += acc[2*np][2] + acc[2*np][3] + acc[2*np+1][2] + acc[2*np+1][3];
            ss0 = fmaf(acc[2*np][0],   acc[2*np][0],   ss0);
            ss0 = fmaf(acc[2*np][1],   acc[2*np][1],   ss0);
            ss0 = fmaf(acc[2*np+1][0], acc[2*np+1][0], ss0);
            ss0 = fmaf(acc[2*np+1][1], acc[2*np+1][1], ss0);
            ss1 = fmaf(acc[2*np][2],   acc[2*np][2],   ss1);
            ss1 = fmaf(acc[2*np][3],   acc[2*np][3],   ss1);
            ss1 = fmaf(acc[2*np+1][2], acc[2*np+1][2], ss1);
            ss1 = fmaf(acc[2*np+1][3], acc[2*np+1][3], ss1);
        }
        s0  += __shfl_xor_sync(0xffffffffu, s0, 1);
        s0  += __shfl_xor_sync(0xffffffffu, s0, 2);
        s1  += __shfl_xor_sync(0xffffffffu, s1, 1);
        s1  += __shfl_xor_sync(0xffffffffu, s1, 2);
        ss0 += __shfl_xor_sync(0xffffffffu, ss0, 1);
        ss0 += __shfl_xor_sync(0xffffffffu, ss0, 2);
        ss1 += __shfl_xor_sync(0xffffffffu, ss1, 1);
        ss1 += __shfl_xor_sync(0xffffffffu, ss1, 2);
        const float mu0 = s0 * (1.f / 128.f);
        const float mu1 = s1 * (1.f / 128.f);
        const float rs0 = rsqrtf(fmaf(-mu0, mu0, ss0 * (1.f / 128.f)) + LN_EPS);
        const float rs1 = rsqrtf(fmaf(-mu1, mu1, ss1 * (1.f / 128.f)) + LN_EPS);

        // C (N-permuted) -> A fragment of GEMM2 (K-permuted identically): free.
        uint32_t a2f[KT2][4];
        #pragma unroll
        for (int np = 0; np < NP1; np++) {
            float4 gg  = *reinterpret_cast<const float4*>(gms + 16 * np + 4 * c4);
            float4 bt4 = *reinterpret_cast<const float4*>(bts + 16 * np + 4 * c4);
            float y00 = silu((acc[2*np][0]   - mu0) * rs0 * gg.x + bt4.x);
            float y01 = silu((acc[2*np][1]   - mu0) * rs0 * gg.y + bt4.y);
            float y10 = silu((acc[2*np][2]   - mu1) * rs1 * gg.x + bt4.x);
            float y11 = silu((acc[2*np][3]   - mu1) * rs1 * gg.y + bt4.y);
            float z00 = silu((acc[2*np+1][0] - mu0) * rs0 * gg.z + bt4.z);
            float z01 = silu((acc[2*np+1][1] - mu0) * rs0 * gg.w + bt4.w);
            float z10 = silu((acc[2*np+1][2] - mu1) * rs1 * gg.z + bt4.z);
            float z11 = silu((acc[2*np+1][3] - mu1) * rs1 * gg.w + bt4.w);
            a2f[np][0] = packh2(y00, y01);  // a0
            a2f[np][1] = packh2(y10, y11);  // a1 (rows +8)
            a2f[np][2] = packh2(z00, z01);  // a2
            a2f[np][3] = packh2(z10, z11);  // a3
        }

        // ================= GEMM2: [16x128] @ W2 -> acc (reused) =================
        #pragma unroll
        for (int nt = 0; nt < NT1; nt++) {
            acc[nt][0] = 0.f; acc[nt][1] = 0.f; acc[nt][2] = 0.f; acc[nt][3] = 0.f;
        }
        #pragma unroll
        for (int kt = 0; kt < KT2; kt++) {
            const uint4* wrow = w2f + (kt * NP1) * 32 + lane;
            #pragma unroll
            for (int np = 0; np < NP1; np++) {
                uint4 B = wrow[np * 32];
                mma16816(acc[2 * np],     a2f[kt][0], a2f[kt][1], a2f[kt][2], a2f[kt][3], B.x, B.y);
                mma16816(acc[2 * np + 1], a2f[kt][0], a2f[kt][1], a2f[kt][2], a2f[kt][3], B.z, B.w);
            }
        }

        // ================= epilogue 2: +b2, SiLU, store (float4) =================
        const bool val0 = (row0 < E);
        const bool val1 = (row1 < E);
        #pragma unroll
        for (int np = 0; np < NP1; np++) {
            float4 bb = *reinterpret_cast<const float4*>(b2s + 16 * np + 4 * c4);
            float4 o0, o1;
            o0.x = silu(acc[2*np][0]   + bb.x);
            o0.y = silu(acc[2*np][1]   + bb.y);
            o0.z = silu(acc[2*np+1][0] + bb.z);
            o0.w = silu(acc[2*np+1][1] + bb.w);
            o1.x = silu(acc[2*np][2]   + bb.x);
            o1.y = silu(acc[2*np][3]   + bb.y);
            o1.z = silu(acc[2*np+1][2] + bb.z);
            o1.w = silu(acc[2*np+1][3] + bb.w);
            const int col = 16 * np + 4 * c4;
            if (val0) *reinterpret_cast<float4*>(out + (size_t)row0 * 128 + col) = o0;
            if (val1) *reinterpret_cast<float4*>(out + (size_t)row1 * 128 + col) = o1;
        }
    }
}

// ===================== launch =====================
extern "C" void kernel_launch(void* const* d_in, const int* in_sizes, int n_in,
                              void* d_out, int out_size)
{
    (void)n_in; (void)out_size;
    const float* src = (const float*)d_in[0];
    const float* edg = (const float*)d_in[1];
    const float* W1  = (const float*)d_in[2];
    const float* b1  = (const float*)d_in[3];
    const float* gma = (const float*)d_in[4];
    const float* bta = (const float*)d_in[5];
    const float* W2  = (const float*)d_in[6];
    const float* b2  = (const float*)d_in[7];
    float* out = (float*)d_out;

    const int E = in_sizes[0] / 128;
    const int n_groups = (E + 15) / 16;

    cudaFuncSetAttribute(edge_mlp_kernel,
                         cudaFuncAttributeMaxDynamicSharedMemorySize, SMEM_BYTES);
    edge_mlp_kernel<<<304, 256, SMEM_BYTES>>>(src, edg, W1, b1, gma, bta, W2, b2,
                                              out, E, n_groups);
}